// round 13
// baseline (speedup 1.0000x reference)
#include <cuda_runtime.h>
#include <cuda_bf16.h>
#include <math.h>

#define TT   512
#define BB   128
#define DIN  102
#define HH   256
#define G4   1024
#define DLIN 128
#define KK   9

// ---------------- device scratch ----------------
// gates layout: [dir][t][col][b]  (fp32)
__device__ float g_gates[(size_t)2 * TT * G4 * BB];
// h layout: bf16 [dir][slot][b][unit] (unit contiguous)
// fwd: slot t+1 = h(t), slot0 zeros; bwd: slot t = h(t), slot TT zeros
__device__ __nv_bfloat16 g_h16[(size_t)2 * (TT + 1) * BB * HH];
__device__ float g_em[(size_t)BB * TT * KK];
// per-CTA step flags: 4 groups (dir x bh) x 32 CTAs, one 128B line per group
__device__ unsigned int g_flags[128];

__device__ __forceinline__ float d2t(float x) {   // round-to-nearest tf32
    float r;
    asm("cvt.rna.tf32.f32 %0, %1;" : "=f"(r) : "f"(x));
    return r;
}
__device__ __forceinline__ unsigned pk2(float lo, float hi) {
    __nv_bfloat162 t = __floats2bfloat162_rn(lo, hi);
    return *(unsigned*)&t;
}
__device__ __forceinline__ void mma8(float* d, const float* a, float b0, float b1) {
    asm volatile(
        "mma.sync.aligned.m16n8k8.row.col.f32.tf32.tf32.f32 "
        "{%0,%1,%2,%3}, {%4,%5,%6,%7}, {%8,%9}, {%0,%1,%2,%3};\n"
        : "+f"(d[0]), "+f"(d[1]), "+f"(d[2]), "+f"(d[3])
        : "r"(__float_as_uint(a[0])), "r"(__float_as_uint(a[1])),
          "r"(__float_as_uint(a[2])), "r"(__float_as_uint(a[3])),
          "r"(__float_as_uint(b0)), "r"(__float_as_uint(b1)));
}
__device__ __forceinline__ void mma16(float* d, const unsigned* a,
                                      unsigned b0, unsigned b1) {
    asm volatile(
        "mma.sync.aligned.m16n8k16.row.col.f32.bf16.bf16.f32 "
        "{%0,%1,%2,%3}, {%4,%5,%6,%7}, {%8,%9}, {%0,%1,%2,%3};\n"
        : "+f"(d[0]), "+f"(d[1]), "+f"(d[2]), "+f"(d[3])
        : "r"(a[0]), "r"(a[1]), "r"(a[2]), "r"(a[3]),
          "r"(b0), "r"(b1));
}
__device__ __forceinline__ float sigf(float x)  { return 1.f / (1.f + __expf(-x)); }
__device__ __forceinline__ float tanhfx(float x){ return 2.f / (1.f + __expf(-2.f * x)) - 1.f; }

// ---------------- kernel 0 ----------------
__global__ void k_zero(float* out) {
    int idx = blockIdx.x * blockDim.x + threadIdx.x;
    int stride = gridDim.x * blockDim.x;
    if (idx == 0) out[0] = 0.f;
    if (idx < 128) g_flags[idx] = 0u;
    const int HBW = BB * HH / 2;   // uints per slot
    unsigned* hf0 = (unsigned*)g_h16;                                        // dir0 slot0
    unsigned* hbT = (unsigned*)(g_h16 + (size_t)((TT + 1) + TT) * BB * HH);  // dir1 slotTT
    for (int i = idx; i < HBW; i += stride) { hf0[i] = 0u; hbT[i] = 0u; }
}

// ---------------- kernel 1: gates = x @ Wih^T + b  (tf32 mma) ------------
__global__ void __launch_bounds__(256) k_proj(
    const float* __restrict__ x,
    const float* __restrict__ Wih_f, const float* __restrict__ b_f,
    const float* __restrict__ Wih_b, const float* __restrict__ b_b)
{
    unsigned bx = blockIdx.x;
    int bh   = bx & 1;
    int colt = (bx >> 1) & 7;
    int t    = (bx >> 4) & 511;
    int dir  = bx >> 13;
    const float* Wih  = dir ? Wih_b : Wih_f;
    const float* bias = dir ? b_b : b_f;
    int col0 = colt * 128;
    int tid = threadIdx.x;
    int lane = tid & 31, w = tid >> 5;
    int q = lane >> 2, tg = lane & 3;
    int rowA = col0 + w * 16 + q;
    int rowB = rowA + 8;

    __shared__ float xs[104][72];

    float aF[13][4];
    #pragma unroll
    for (int kk = 0; kk < 13; ++kk) {
        int k = kk * 8 + tg;
        aF[kk][0] = (k < DIN)     ? d2t(Wih[(size_t)rowA * DIN + k])     : 0.f;
        aF[kk][1] = (k < DIN)     ? d2t(Wih[(size_t)rowB * DIN + k])     : 0.f;
        aF[kk][2] = (k + 4 < DIN) ? d2t(Wih[(size_t)rowA * DIN + k + 4]) : 0.f;
        aF[kk][3] = (k + 4 < DIN) ? d2t(Wih[(size_t)rowB * DIN + k + 4]) : 0.f;
    }
    for (int i = tid; i < 2 * 64; i += 256) xs[102 + (i >> 6)][i & 63] = 0.f;
    for (int f = tid; f < 64 * DIN; f += 256) {
        int b = f / DIN, d = f - b * DIN;
        xs[d][b] = d2t(x[((size_t)(bh * 64 + b) * TT + t) * DIN + d]);
    }
    __syncthreads();

    float acc[8][4];
    #pragma unroll
    for (int nt = 0; nt < 8; ++nt)
        #pragma unroll
        for (int j = 0; j < 4; ++j) acc[nt][j] = 0.f;

    #pragma unroll
    for (int kk = 0; kk < 13; ++kk) {
        #pragma unroll
        for (int nt = 0; nt < 8; ++nt) {
            float b0 = xs[kk * 8 + tg][nt * 8 + q];
            float b1 = xs[kk * 8 + tg + 4][nt * 8 + q];
            mma8(acc[nt], aF[kk], b0, b1);
        }
    }

    float bA = bias[rowA], bB = bias[rowB];
    float* gt = g_gates + ((size_t)(dir * TT + t)) * (G4 * BB);
    #pragma unroll
    for (int nt = 0; nt < 8; ++nt) {
        int cb = bh * 64 + nt * 8 + 2 * tg;
        *(float2*)&gt[(size_t)rowA * BB + cb] = make_float2(acc[nt][0] + bA, acc[nt][1] + bA);
        *(float2*)&gt[(size_t)rowB * BB + cb] = make_float2(acc[nt][2] + bB, acc[nt][3] + bB);
    }
}

// ---------------- kernel 2: persistent BiLSTM, bf16 mma, reg cell state --
// 128 CTAs: dir(2) x ug(32) x bh(2); 256 thr. 32 gate rows x 64 batch.
// Warp owns 4 units x ALL 4 gates (rowA={i,f}, rowB={g,o}); one shfl.xor 16
// assembles the gate quad; cell state lives in 2 registers per lane.
// Barrier = per-CTA flag words (one 128B line per group), st.release +
// warp-wide acquire poll.
__global__ void __launch_bounds__(256, 1) k_rnn(
    const float* __restrict__ Whh_f, const float* __restrict__ Whh_b)
{
    int tid  = threadIdx.x;
    int lane = tid & 31, w = tid >> 5;
    int mh = w >> 2;                  // 0..1: unit quad
    int ng = w & 3;                   // 0..3: 16-batch group
    int dir = blockIdx.x >> 6;
    int sub = blockIdx.x & 63;
    int ug  = sub >> 1;               // 0..31
    int bh  = sub & 1;
    int u0  = ug * 8;
    int boff = bh * 64;
    const float* Whh = dir ? Whh_b : Whh_f;

    __shared__ unsigned hsW[64 * 132];        // h tile [b][k] bf16 pairs
    __shared__ __nv_bfloat16 hb[64][8];       // h out staging [b][u]

    int q  = lane >> 2;
    int tg = lane & 3;
    // rowA: q<4 -> gate i, q>=4 -> gate f (units u0+mh*4+(q&3))
    int rowA = (q >> 2) * 256 + u0 + mh * 4 + (q & 3);
    int rowB = rowA + 512;            // g / o
    int n0 = ng * 16;

    // bf16 A fragments: 32 rows x 256 k of Whh in 64 regs
    unsigned aF[16][4];
    {
        const float* WA = Whh + (size_t)rowA * HH;
        const float* WB = Whh + (size_t)rowB * HH;
        #pragma unroll
        for (int kk = 0; kk < 16; ++kk) {
            int k0 = kk * 16 + 2 * tg;
            float2 a0 = *(const float2*)&WA[k0];
            float2 a1 = *(const float2*)&WB[k0];
            float2 a2 = *(const float2*)&WA[k0 + 8];
            float2 a3 = *(const float2*)&WB[k0 + 8];
            aF[kk][0] = pk2(a0.x, a0.y);
            aF[kk][1] = pk2(a1.x, a1.y);
            aF[kk][2] = pk2(a2.x, a2.y);
            aF[kk][3] = pk2(a3.x, a3.y);
        }
    }

    const size_t HB = (size_t)BB * HH;
    __nv_bfloat16* harr = g_h16 + (size_t)dir * (TT + 1) * HB;
    const float* gbase = g_gates + (size_t)dir * TT * (size_t)(G4 * BB);
    int bidx = dir * 2 + bh;
    unsigned int* flag_me  = &g_flags[bidx * 32 + ug];
    unsigned int* flag_grp = &g_flags[bidx * 32];
    int cb = boff + n0 + 2 * tg;

    float2 gA[2], gB[2];
    {
        int t0 = dir ? (TT - 1) : 0;
        const float* gt = gbase + (size_t)t0 * (G4 * BB);
        #pragma unroll
        for (int nt = 0; nt < 2; ++nt) {
            gA[nt] = *(const float2*)&gt[(size_t)rowA * BB + cb + nt * 8];
            gB[nt] = *(const float2*)&gt[(size_t)rowB * BB + cb + nt * 8];
        }
    }

    int srow = tid >> 5;      // 0..7
    int scol = tid & 31;      // 16B column
    int half = q >> 2;        // which nt this lane finalizes
    int unit = mh * 4 + (q & 3);
    int cbE  = n0 + half * 8 + 2 * tg;   // local epilogue cols
    float c0 = 0.f, c1 = 0.f;            // cell state in registers

    for (int s = 0; s < TT; ++s) {
        int t = dir ? (TT - 1 - s) : s;
        const __nv_bfloat16* hin = harr + (size_t)(dir ? (t + 1) : t) * HB
                                        + (size_t)boff * HH;
        __nv_bfloat16* hout = harr + (size_t)(dir ? t : (t + 1)) * HB;

        // wait for all 32 producer CTAs of this group to finish step s-1
        if (s) {
            if (tid < 32) {
                unsigned v;
                do {
                    asm volatile("ld.acquire.gpu.global.u32 %0, [%1];"
                                 : "=r"(v) : "l"(flag_grp + tid));
                } while (!__all_sync(0xffffffffu, v >= (unsigned)s));
            }
            __syncthreads();
        }

        // stage h tile [64 b][256 k] bf16 -> smem (coalesced LDG.128)
        uint4 v[8];
        #pragma unroll
        for (int i = 0; i < 8; ++i)
            v[i] = ((const uint4*)(hin + (size_t)(srow + 8 * i) * HH))[scol];
        #pragma unroll
        for (int i = 0; i < 8; ++i)
            *(uint4*)&hsW[(srow + 8 * i) * 132 + scol * 4] = v[i];
        __syncthreads();

        float acc[2][4];
        #pragma unroll
        for (int nt = 0; nt < 2; ++nt) {
            acc[nt][0] = gA[nt].x; acc[nt][1] = gA[nt].y;
            acc[nt][2] = gB[nt].x; acc[nt][3] = gB[nt].y;
        }
        #pragma unroll
        for (int kk = 0; kk < 16; ++kk) {
            #pragma unroll
            for (int nt = 0; nt < 2; ++nt) {
                int base = (n0 + nt * 8 + q) * 132 + kk * 8 + tg;
                mma16(acc[nt], aF[kk], hsW[base], hsW[base + 4]);
            }
        }

        // gate-quad exchange: lane^16 swaps q<->q+4 (i,g)<->(f,o)
        float p0[4], p1[4];
        #pragma unroll
        for (int j = 0; j < 4; ++j) {
            p0[j] = __shfl_xor_sync(0xffffffffu, acc[0][j], 16);
            p1[j] = __shfl_xor_sync(0xffffffffu, acc[1][j], 16);
        }
        float iv0, iv1, gv0, gv1, fv0, fv1, ov0, ov1;
        if (half == 0) {      // finalize nt=0; own acc[0]=(i,g), partner p0=(f,o)
            iv0 = acc[0][0]; iv1 = acc[0][1]; gv0 = acc[0][2]; gv1 = acc[0][3];
            fv0 = p0[0];     fv1 = p0[1];     ov0 = p0[2];     ov1 = p0[3];
        } else {              // finalize nt=1; own acc[1]=(f,o), partner p1=(i,g)
            fv0 = acc[1][0]; fv1 = acc[1][1]; ov0 = acc[1][2]; ov1 = acc[1][3];
            iv0 = p1[0];     iv1 = p1[1];     gv0 = p1[2];     gv1 = p1[3];
        }
        c0 = sigf(fv0) * c0 + sigf(iv0) * tanhfx(gv0);
        c1 = sigf(fv1) * c1 + sigf(iv1) * tanhfx(gv1);
        hb[cbE][unit]     = __float2bfloat16_rn(sigf(ov0) * tanhfx(c0));
        hb[cbE + 1][unit] = __float2bfloat16_rn(sigf(ov1) * tanhfx(c1));
        __syncthreads();

        // cooperative h writeback: 64 threads x 16B
        if (tid < 64) {
            uint4 hv = *(uint4*)&hb[tid][0];
            *(uint4*)(hout + (size_t)(boff + tid) * HH + u0) = hv;
        }
        __syncthreads();
        if (tid == 0) {
            unsigned sv = (unsigned)(s + 1);
            asm volatile("st.release.gpu.global.u32 [%0], %1;"
                         :: "l"(flag_me), "r"(sv) : "memory");
        }

        // prefetch next step's gates (independent of the flags)
        if (s + 1 < TT) {
            int tn = dir ? (t - 1) : (t + 1);
            const float* gt = gbase + (size_t)tn * (G4 * BB);
            #pragma unroll
            for (int nt = 0; nt < 2; ++nt) {
                gA[nt] = *(const float2*)&gt[(size_t)rowA * BB + cb + nt * 8];
                gB[nt] = *(const float2*)&gt[(size_t)rowB * BB + cb + nt * 8];
            }
        }
    }
}

// ---------------- kernel 3: feats + emissions (bf16 mma) -----------------
__global__ void __launch_bounds__(256) k_feats(
    const float* __restrict__ Wlin, const float* __restrict__ blin,
    const float* __restrict__ Wcls, const float* __restrict__ bcls)
{
    unsigned bx = blockIdx.x;
    int bh = bx & 1;
    int t  = bx >> 1;
    int tid = threadIdx.x;
    int lane = tid & 31, w = tid >> 5;
    int q = lane >> 2, tg = lane & 3;

    __shared__ float smem[9616];
    unsigned* hsW = (unsigned*)smem;          // phase1: [64 b][36w] h chunk
    unsigned* Ws2 = (unsigned*)(smem + 2304); // phase1: [128 n][36w] Wlin chunk
    float* Fs = smem;                         // phase2: [64][132] feats
    float* Wc = smem + 8448;                  // [9][128]
    float* bc = smem + 9600;                  // [9]

    for (int i = tid; i < KK * DLIN; i += 256) Wc[i] = Wcls[i];
    if (tid < KK) bc[tid] = bcls[tid];

    int n0w = w * 16;
    float acc[8][4];
    #pragma unroll
    for (int nt = 0; nt < 8; ++nt)
        #pragma unroll
        for (int j = 0; j < 4; ++j) acc[nt][j] = 0.f;

    const size_t HB = (size_t)BB * HH;
    const __nv_bfloat16* hf = g_h16 + (size_t)(t + 1) * HB + (size_t)(bh * 64) * HH;
    const __nv_bfloat16* hb = g_h16 + (size_t)(TT + 1) * HB + (size_t)t * HB
                                    + (size_t)(bh * 64) * HH;

    int wrow = tid >> 1, wpart = tid & 1;
    int hrow0 = tid >> 3, hc8 = tid & 7;

    for (int kc = 0; kc < 8; ++kc) {
        __syncthreads();
        int kbase = (kc & 3) * 64;
        const __nv_bfloat16* hsrc = (kc < 4) ? hf : hb;
        #pragma unroll
        for (int i = 0; i < 2; ++i) {
            int row = hrow0 + 32 * i;
            uint4 hv = *(const uint4*)(hsrc + (size_t)row * HH + kbase + hc8 * 8);
            *(uint4*)&hsW[row * 36 + hc8 * 4] = hv;
        }
        int kglob = kc * 64;
        #pragma unroll
        for (int j = 0; j < 8; ++j) {
            float4 vv = *(const float4*)&Wlin[(size_t)wrow * 512 + kglob + wpart * 32 + j * 4];
            unsigned w0 = pk2(vv.x, vv.y);
            unsigned w1 = pk2(vv.z, vv.w);
            *(uint2*)&Ws2[wrow * 36 + wpart * 16 + j * 2] = make_uint2(w0, w1);
        }
        __syncthreads();
        #pragma unroll
        for (int kk = 0; kk < 4; ++kk) {
            unsigned a[4];
            int ab = (n0w + q) * 36 + kk * 8 + tg;
            a[0] = Ws2[ab];
            a[1] = Ws2[ab + 8 * 36];
            a[2] = Ws2[ab + 4];
            a[3] = Ws2[ab + 8 * 36 + 4];
            #pragma unroll
            for (int nt = 0; nt < 8; ++nt) {
                int bbse = (nt * 8 + q) * 36 + kk * 8 + tg;
                mma16(acc[nt], a, hsW[bbse], hsW[bbse + 4]);
            }
        }
    }
    __syncthreads();

    float blA = blin[n0w + q], blB = blin[n0w + q + 8];
    #pragma unroll
    for (int nt = 0; nt < 8; ++nt) {
        int b = nt * 8 + 2 * tg;
        float v0 = acc[nt][0] + blA;
        float v1 = acc[nt][1] + blA;
        float v2 = acc[nt][2] + blB;
        float v3 = acc[nt][3] + blB;
        v0 = (v0 > 0.f) ? v0 : expm1f(v0);
        v1 = (v1 > 0.f) ? v1 : expm1f(v1);
        v2 = (v2 > 0.f) ? v2 : expm1f(v2);
        v3 = (v3 > 0.f) ? v3 : expm1f(v3);
        Fs[b * 132 + n0w + q] = v0;
        Fs[(b + 1) * 132 + n0w + q] = v1;
        Fs[b * 132 + n0w + q + 8] = v2;
        Fs[(b + 1) * 132 + n0w + q + 8] = v3;
    }
    __syncthreads();

    for (int p = tid; p < 64 * KK; p += 256) {
        int b = p / KK, k9 = p % KK;
        const float4* fr = (const float4*)&Fs[b * 132];
        const float4* wr = (const float4*)&Wc[k9 * 128];
        float s = 0.f;
        #pragma unroll
        for (int i = 0; i < 32; ++i) {
            float4 f = fr[i], ww = wr[i];
            s += f.x * ww.x + f.y * ww.y + f.z * ww.z + f.w * ww.w;
        }
        int bg = bh * 64 + b;
        g_em[((size_t)bg * TT + t) * KK + k9] = s + bc[k9];
    }
}

// ---------------- kernel 4: CRF NLL --------------------------------------
__global__ void k_crf(const int* __restrict__ labels,
                      const float* __restrict__ start_t,
                      const float* __restrict__ end_t,
                      const float* __restrict__ trans,
                      float* out)
{
    int b = blockIdx.x;
    int j = threadIdx.x;
    const float* em = g_em + (size_t)b * TT * KK;
    int jj = (j < KK) ? j : 0;
    float tr[KK];
    #pragma unroll
    for (int i = 0; i < KK; ++i) tr[i] = trans[i * KK + jj];

    float alpha = (j < KK) ? (start_t[j] + em[j]) : -1e30f;
    for (int t = 1; t < TT; ++t) {
        float e = (j < KK) ? em[t * KK + j] : 0.f;
        float v[KK];
        float m = -1e30f;
        #pragma unroll
        for (int i = 0; i < KK; ++i) {
            float ai = __shfl_sync(0xffffffffu, alpha, i);
            v[i] = ai + tr[i];
            m = fmaxf(m, v[i]);
        }
        float s = 0.f;
        #pragma unroll
        for (int i = 0; i < KK; ++i) s += expf(v[i] - m);
        float na = m + logf(s) + e;
        alpha = (j < KK) ? na : -1e30f;
    }
    float z = (j < KK) ? (alpha + end_t[j]) : -1e30f;
    float m = z;
    #pragma unroll
    for (int o = 16; o > 0; o >>= 1) m = fmaxf(m, __shfl_xor_sync(0xffffffffu, m, o));
    float s = (j < KK) ? expf(z - m) : 0.f;
    #pragma unroll
    for (int o = 16; o > 0; o >>= 1) s += __shfl_xor_sync(0xffffffffu, s, o);
    float logZ = m + logf(s);

    const int* lb = labels + (size_t)b * TT;
    float part = 0.f;
    for (int t = 1 + j; t < TT; t += 32) {
        int lp = lb[t - 1], lc = lb[t];
        part += trans[lp * KK + lc] + em[t * KK + lc];
    }
    #pragma unroll
    for (int o = 16; o > 0; o >>= 1) part += __shfl_xor_sync(0xffffffffu, part, o);

    if (j == 0) {
        int l0 = lb[0];
        float num = part + start_t[l0] + em[l0] + end_t[lb[TT - 1]];
        atomicAdd(out, logZ - num);
    }
}

// ---------------- host launcher ------------------------------------------
extern "C" void kernel_launch(void* const* d_in, const int* in_sizes, int n_in,
                              void* d_out, int out_size) {
    const float* x      = (const float*)d_in[0];
    const int*   labels = (const int*)d_in[2];
    const float* Wih_f  = (const float*)d_in[4];
    const float* Whh_f  = (const float*)d_in[5];
    const float* b_f    = (const float*)d_in[6];
    const float* Wih_b  = (const float*)d_in[7];
    const float* Whh_b  = (const float*)d_in[8];
    const float* b_b    = (const float*)d_in[9];
    const float* Wlin   = (const float*)d_in[10];
    const float* blin   = (const float*)d_in[11];
    const float* Wcls   = (const float*)d_in[12];
    const float* bcls   = (const float*)d_in[13];
    const float* start_t= (const float*)d_in[14];
    const float* end_t  = (const float*)d_in[15];
    const float* trans  = (const float*)d_in[16];
    float* out = (float*)d_out;

    k_zero<<<64, 256>>>(out);
    k_proj<<<16384, 256>>>(x, Wih_f, b_f, Wih_b, b_b);
    k_rnn<<<128, 256>>>(Whh_f, Whh_b);
    k_feats<<<1024, 256>>>(Wlin, blin, Wcls, bcls);
    k_crf<<<128, 32>>>(labels, start_t, end_t, trans, out);
}

// round 14
// speedup vs baseline: 1.3129x; 1.3129x over previous
#include <cuda_runtime.h>
#include <cuda_bf16.h>
#include <math.h>

#define TT   512
#define BB   128
#define DIN  102
#define HH   256
#define G4   1024
#define DLIN 128
#define KK   9

// ---------------- device scratch ----------------
// gates layout: [dir][t][col][b]  (fp32)
__device__ float g_gates[(size_t)2 * TT * G4 * BB];
// h layout: bf16 [dir][slot][b][unit] (unit contiguous)
// fwd: slot t+1 = h(t), slot0 zeros; bwd: slot t = h(t), slot TT zeros
__device__ __nv_bfloat16 g_h16[(size_t)2 * (TT + 1) * BB * HH];
__device__ float g_em[(size_t)BB * TT * KK];
__device__ unsigned int g_bar4[4];
// Wlin pre-converted to bf16 pairs: [128 n][512 k] -> 32768 uints
__device__ unsigned g_wlin16[DLIN * 512 / 2];

__device__ __forceinline__ float d2t(float x) {   // round-to-nearest tf32
    float r;
    asm("cvt.rna.tf32.f32 %0, %1;" : "=f"(r) : "f"(x));
    return r;
}
__device__ __forceinline__ unsigned pk2(float lo, float hi) {
    __nv_bfloat162 t = __floats2bfloat162_rn(lo, hi);
    return *(unsigned*)&t;
}
__device__ __forceinline__ void mma8(float* d, const float* a, float b0, float b1) {
    asm volatile(
        "mma.sync.aligned.m16n8k8.row.col.f32.tf32.tf32.f32 "
        "{%0,%1,%2,%3}, {%4,%5,%6,%7}, {%8,%9}, {%0,%1,%2,%3};\n"
        : "+f"(d[0]), "+f"(d[1]), "+f"(d[2]), "+f"(d[3])
        : "r"(__float_as_uint(a[0])), "r"(__float_as_uint(a[1])),
          "r"(__float_as_uint(a[2])), "r"(__float_as_uint(a[3])),
          "r"(__float_as_uint(b0)), "r"(__float_as_uint(b1)));
}
__device__ __forceinline__ void mma16(float* d, const unsigned* a,
                                      unsigned b0, unsigned b1) {
    asm volatile(
        "mma.sync.aligned.m16n8k16.row.col.f32.bf16.bf16.f32 "
        "{%0,%1,%2,%3}, {%4,%5,%6,%7}, {%8,%9}, {%0,%1,%2,%3};\n"
        : "+f"(d[0]), "+f"(d[1]), "+f"(d[2]), "+f"(d[3])
        : "r"(a[0]), "r"(a[1]), "r"(a[2]), "r"(a[3]),
          "r"(b0), "r"(b1));
}
__device__ __forceinline__ float sigf(float x)  { return 1.f / (1.f + __expf(-x)); }
__device__ __forceinline__ float tanhfx(float x){ return 2.f / (1.f + __expf(-2.f * x)) - 1.f; }

// ---------------- kernel 0: init + Wlin bf16 pre-convert -----------------
__global__ void k_zero(float* out, const float* __restrict__ Wlin) {
    int idx = blockIdx.x * blockDim.x + threadIdx.x;
    int stride = gridDim.x * blockDim.x;
    if (idx == 0) {
        g_bar4[0] = 0u; g_bar4[1] = 0u; g_bar4[2] = 0u; g_bar4[3] = 0u;
        out[0] = 0.f;
    }
    const int HBW = BB * HH / 2;   // uints per slot
    unsigned* hf0 = (unsigned*)g_h16;                                        // dir0 slot0
    unsigned* hbT = (unsigned*)(g_h16 + (size_t)((TT + 1) + TT) * BB * HH);  // dir1 slotTT
    for (int i = idx; i < HBW; i += stride) { hf0[i] = 0u; hbT[i] = 0u; }
    // Wlin fp32 -> bf16 pairs
    for (int i = idx; i < DLIN * 512 / 2; i += stride) {
        float2 v = ((const float2*)Wlin)[i];
        g_wlin16[i] = pk2(v.x, v.y);
    }
}

// ---------------- kernel 1: gates = x @ Wih^T + b  (tf32 mma) ------------
__global__ void __launch_bounds__(256) k_proj(
    const float* __restrict__ x,
    const float* __restrict__ Wih_f, const float* __restrict__ b_f,
    const float* __restrict__ Wih_b, const float* __restrict__ b_b)
{
    unsigned bx = blockIdx.x;
    int bh   = bx & 1;
    int colt = (bx >> 1) & 7;
    int t    = (bx >> 4) & 511;
    int dir  = bx >> 13;
    const float* Wih  = dir ? Wih_b : Wih_f;
    const float* bias = dir ? b_b : b_f;
    int col0 = colt * 128;
    int tid = threadIdx.x;
    int lane = tid & 31, w = tid >> 5;
    int q = lane >> 2, tg = lane & 3;
    int rowA = col0 + w * 16 + q;
    int rowB = rowA + 8;

    __shared__ float xs[104][72];

    float aF[13][4];
    #pragma unroll
    for (int kk = 0; kk < 13; ++kk) {
        int k = kk * 8 + tg;
        aF[kk][0] = (k < DIN)     ? d2t(Wih[(size_t)rowA * DIN + k])     : 0.f;
        aF[kk][1] = (k < DIN)     ? d2t(Wih[(size_t)rowB * DIN + k])     : 0.f;
        aF[kk][2] = (k + 4 < DIN) ? d2t(Wih[(size_t)rowA * DIN + k + 4]) : 0.f;
        aF[kk][3] = (k + 4 < DIN) ? d2t(Wih[(size_t)rowB * DIN + k + 4]) : 0.f;
    }
    for (int i = tid; i < 2 * 64; i += 256) xs[102 + (i >> 6)][i & 63] = 0.f;
    for (int f = tid; f < 64 * DIN; f += 256) {
        int b = f / DIN, d = f - b * DIN;
        xs[d][b] = d2t(x[((size_t)(bh * 64 + b) * TT + t) * DIN + d]);
    }
    __syncthreads();

    float acc[8][4];
    #pragma unroll
    for (int nt = 0; nt < 8; ++nt)
        #pragma unroll
        for (int j = 0; j < 4; ++j) acc[nt][j] = 0.f;

    #pragma unroll
    for (int kk = 0; kk < 13; ++kk) {
        #pragma unroll
        for (int nt = 0; nt < 8; ++nt) {
            float b0 = xs[kk * 8 + tg][nt * 8 + q];
            float b1 = xs[kk * 8 + tg + 4][nt * 8 + q];
            mma8(acc[nt], aF[kk], b0, b1);
        }
    }

    float bA = bias[rowA], bB = bias[rowB];
    float* gt = g_gates + ((size_t)(dir * TT + t)) * (G4 * BB);
    #pragma unroll
    for (int nt = 0; nt < 8; ++nt) {
        int cb = bh * 64 + nt * 8 + 2 * tg;
        *(float2*)&gt[(size_t)rowA * BB + cb] = make_float2(acc[nt][0] + bA, acc[nt][1] + bA);
        *(float2*)&gt[(size_t)rowB * BB + cb] = make_float2(acc[nt][2] + bB, acc[nt][3] + bB);
    }
}

// ---------------- kernel 2: persistent BiLSTM, bf16 mma (R11 version) ----
// 128 CTAs: dir(2) x ug(32) x bh(2); 256 thr. 32 gate rows x 64 batch.
__global__ void __launch_bounds__(256, 1) k_rnn(
    const float* __restrict__ Whh_f, const float* __restrict__ Whh_b)
{
    int tid  = threadIdx.x;
    int lane = tid & 31, w = tid >> 5;
    int mg = w >> 2;                  // 0..1: gate pair (i,f)/(g,o)
    int ng = w & 3;                   // 0..3: 16-batch group
    int dir = blockIdx.x >> 6;
    int sub = blockIdx.x & 63;
    int ug  = sub >> 1;
    int bh  = sub & 1;
    int u0  = ug * 8;
    int boff = bh * 64;
    const float* Whh = dir ? Whh_b : Whh_f;

    __shared__ unsigned hsW[64 * 132];        // h tile [b][k] bf16, pitch 132 words
    __shared__ float outs[32][72];            // pre-activation gates
    __shared__ float csh[8][64];              // cell state [u][b]
    __shared__ __nv_bfloat16 hb[64][8];       // h out staging [b][u]

    int q  = lane >> 2;
    int tg = lane & 3;
    int rowA = (2 * mg) * 256 + u0 + q;
    int rowB = rowA + 256;
    int n0 = ng * 16;

    // bf16 A fragments: 32 rows x 256 k of Whh in 64 regs
    unsigned aF[16][4];
    {
        const float* WA = Whh + (size_t)rowA * HH;
        const float* WB = Whh + (size_t)rowB * HH;
        #pragma unroll
        for (int kk = 0; kk < 16; ++kk) {
            int k0 = kk * 16 + 2 * tg;
            float2 a0 = *(const float2*)&WA[k0];
            float2 a1 = *(const float2*)&WB[k0];
            float2 a2 = *(const float2*)&WA[k0 + 8];
            float2 a3 = *(const float2*)&WB[k0 + 8];
            aF[kk][0] = pk2(a0.x, a0.y);
            aF[kk][1] = pk2(a1.x, a1.y);
            aF[kk][2] = pk2(a2.x, a2.y);
            aF[kk][3] = pk2(a3.x, a3.y);
        }
    }
    for (int i = tid; i < 8 * 64; i += 256) ((float*)csh)[i] = 0.f;
    __syncthreads();

    const size_t HB = (size_t)BB * HH;
    __nv_bfloat16* harr = g_h16 + (size_t)dir * (TT + 1) * HB;
    const float* gbase = g_gates + (size_t)dir * TT * (size_t)(G4 * BB);
    unsigned bidx = (unsigned)(dir * 2 + bh);
    unsigned int* barp = &g_bar4[bidx];
    int cb = boff + n0 + 2 * tg;

    float2 gA[2], gB[2];
    {
        int t0 = dir ? (TT - 1) : 0;
        const float* gt = gbase + (size_t)t0 * (G4 * BB);
        #pragma unroll
        for (int nt = 0; nt < 2; ++nt) {
            gA[nt] = *(const float2*)&gt[(size_t)rowA * BB + cb + nt * 8];
            gB[nt] = *(const float2*)&gt[(size_t)rowB * BB + cb + nt * 8];
        }
    }

    int srow = tid >> 5;      // 0..7
    int scol = tid & 31;      // 16B column

    for (int s = 0; s < TT; ++s) {
        int t = dir ? (TT - 1 - s) : s;
        const __nv_bfloat16* hin = harr + (size_t)(dir ? (t + 1) : t) * HB
                                        + (size_t)boff * HH;
        __nv_bfloat16* hout = harr + (size_t)(dir ? t : (t + 1)) * HB;

        // stage h tile [64 b][256 k] bf16 -> smem (coalesced LDG.128)
        uint4 v[8];
        #pragma unroll
        for (int i = 0; i < 8; ++i)
            v[i] = ((const uint4*)(hin + (size_t)(srow + 8 * i) * HH))[scol];
        #pragma unroll
        for (int i = 0; i < 8; ++i)
            *(uint4*)&hsW[(srow + 8 * i) * 132 + scol * 4] = v[i];
        __syncthreads();

        float acc[2][4] = {{0.f,0.f,0.f,0.f},{0.f,0.f,0.f,0.f}};
        #pragma unroll
        for (int kk = 0; kk < 16; ++kk) {
            #pragma unroll
            for (int nt = 0; nt < 2; ++nt) {
                int base = (n0 + nt * 8 + q) * 132 + kk * 8 + tg;
                unsigned b0 = hsW[base];
                unsigned b1 = hsW[base + 4];
                mma16(acc[nt], aF[kk], b0, b1);
            }
        }

        // add input-projection gates (fp32), stage to outs
        #pragma unroll
        for (int nt = 0; nt < 2; ++nt) {
            acc[nt][0] += gA[nt].x; acc[nt][1] += gA[nt].y;
            acc[nt][2] += gB[nt].x; acc[nt][3] += gB[nt].y;
            *(float2*)&outs[mg * 16 + q][n0 + nt * 8 + 2 * tg] =
                make_float2(acc[nt][0], acc[nt][1]);
            *(float2*)&outs[mg * 16 + q + 8][n0 + nt * 8 + 2 * tg] =
                make_float2(acc[nt][2], acc[nt][3]);
        }
        __syncthreads();

        // LSTM cell epilogue: 8 units x 64 cols
        #pragma unroll
        for (int rep = 0; rep < 2; ++rep) {
            int p = tid + rep * 256;
            int u = p >> 6, cc = p & 63;
            float iv = outs[u][cc];
            float fv = outs[8 + u][cc];
            float gv = outs[16 + u][cc];
            float ov = outs[24 + u][cc];
            float c = sigf(fv) * csh[u][cc] + sigf(iv) * tanhfx(gv);
            csh[u][cc] = c;
            float h = sigf(ov) * tanhfx(c);
            hb[cc][u] = __float2bfloat16_rn(h);
        }
        __syncthreads();

        // cooperative h writeback: 64 threads x 16B
        if (tid < 64) {
            uint4 hv = *(uint4*)&hb[tid][0];
            *(uint4*)(hout + (size_t)(boff + tid) * HH + u0) = hv;
        }
        __syncthreads();
        if (tid == 0) {
            unsigned one = 1u;
            asm volatile("red.release.gpu.global.add.u32 [%0], %1;"
                         :: "l"(barp), "r"(one) : "memory");
        }

        // prefetch next step's gates while the barrier drains
        if (s + 1 < TT) {
            int tn = dir ? (t - 1) : (t + 1);
            const float* gt = gbase + (size_t)tn * (G4 * BB);
            #pragma unroll
            for (int nt = 0; nt < 2; ++nt) {
                gA[nt] = *(const float2*)&gt[(size_t)rowA * BB + cb + nt * 8];
                gB[nt] = *(const float2*)&gt[(size_t)rowB * BB + cb + nt * 8];
            }
        }
        if (tid == 0) {
            unsigned target = (unsigned)(s + 1) * 32u;
            while (*((volatile unsigned int*)barp) < target) {}
        }
        __syncthreads();
    }
}

// ---------------- kernel 3: feats + emissions (bf16 mma, double-buffered) -
__global__ void __launch_bounds__(256) k_feats(
    const float* __restrict__ blin,
    const float* __restrict__ Wcls, const float* __restrict__ bcls)
{
    unsigned bx = blockIdx.x;
    int bh = bx & 1;
    int t  = bx >> 1;
    int tid = threadIdx.x;
    int lane = tid & 31, w = tid >> 5;
    int q = lane >> 2, tg = lane & 3;

    __shared__ float smem[9616];
    unsigned* hsW = (unsigned*)smem;          // phase1: [64 b][36w] h chunk
    unsigned* Ws2 = (unsigned*)(smem + 2304); // phase1: [128 n][36w] Wlin chunk
    float* Fs = smem;                         // phase2: [64][132] feats
    float* Wc = smem + 8448;                  // [9][128]
    float* bc = smem + 9600;                  // [9]

    for (int i = tid; i < KK * DLIN; i += 256) Wc[i] = Wcls[i];
    if (tid < KK) bc[tid] = bcls[tid];

    int n0w = w * 16;
    float acc[8][4];
    #pragma unroll
    for (int nt = 0; nt < 8; ++nt)
        #pragma unroll
        for (int j = 0; j < 4; ++j) acc[nt][j] = 0.f;

    const size_t HB = (size_t)BB * HH;
    const __nv_bfloat16* hf = g_h16 + (size_t)(t + 1) * HB + (size_t)(bh * 64) * HH;
    const __nv_bfloat16* hb = g_h16 + (size_t)(TT + 1) * HB + (size_t)t * HB
                                    + (size_t)(bh * 64) * HH;
    const uint4* wl4 = (const uint4*)g_wlin16;

    int hrow0 = tid >> 3, hc8 = tid & 7;      // h staging
    int wrow = tid >> 1, wpart = tid & 1;     // Wlin staging

    // prefetch chunk 0
    uint4 hv[2], wv[4];
    {
        const __nv_bfloat16* hsrc = hf;
        #pragma unroll
        for (int i = 0; i < 2; ++i)
            hv[i] = *(const uint4*)(hsrc + (size_t)(hrow0 + 32 * i) * HH + hc8 * 8);
        #pragma unroll
        for (int j = 0; j < 4; ++j)
            wv[j] = wl4[wrow * 64 + wpart * 4 + j];
    }

    for (int kc = 0; kc < 8; ++kc) {
        __syncthreads();      // previous mma finished reading smem
        #pragma unroll
        for (int i = 0; i < 2; ++i)
            *(uint4*)&hsW[(hrow0 + 32 * i) * 36 + hc8 * 4] = hv[i];
        #pragma unroll
        for (int j = 0; j < 4; ++j)
            *(uint4*)&Ws2[wrow * 36 + wpart * 16 + j * 4] = wv[j];
        __syncthreads();

        // prefetch next chunk (overlaps this chunk's mma)
        if (kc + 1 < 8) {
            int kn = kc + 1;
            int kbase = (kn & 3) * 64;
            const __nv_bfloat16* hsrc = (kn < 4) ? hf : hb;
            #pragma unroll
            for (int i = 0; i < 2; ++i)
                hv[i] = *(const uint4*)(hsrc + (size_t)(hrow0 + 32 * i) * HH + kbase + hc8 * 8);
            #pragma unroll
            for (int j = 0; j < 4; ++j)
                wv[j] = wl4[wrow * 64 + kn * 8 + wpart * 4 + j];
        }

        #pragma unroll
        for (int kk = 0; kk < 4; ++kk) {
            unsigned a[4];
            int ab = (n0w + q) * 36 + kk * 8 + tg;
            a[0] = Ws2[ab];
            a[1] = Ws2[ab + 8 * 36];
            a[2] = Ws2[ab + 4];
            a[3] = Ws2[ab + 8 * 36 + 4];
            #pragma unroll
            for (int nt = 0; nt < 8; ++nt) {
                int bbse = (nt * 8 + q) * 36 + kk * 8 + tg;
                mma16(acc[nt], a, hsW[bbse], hsW[bbse + 4]);
            }
        }
    }
    __syncthreads();

    float blA = blin[n0w + q], blB = blin[n0w + q + 8];
    #pragma unroll
    for (int nt = 0; nt < 8; ++nt) {
        int b = nt * 8 + 2 * tg;
        float v0 = acc[nt][0] + blA;
        float v1 = acc[nt][1] + blA;
        float v2 = acc[nt][2] + blB;
        float v3 = acc[nt][3] + blB;
        v0 = (v0 > 0.f) ? v0 : expm1f(v0);
        v1 = (v1 > 0.f) ? v1 : expm1f(v1);
        v2 = (v2 > 0.f) ? v2 : expm1f(v2);
        v3 = (v3 > 0.f) ? v3 : expm1f(v3);
        Fs[b * 132 + n0w + q] = v0;
        Fs[(b + 1) * 132 + n0w + q] = v1;
        Fs[b * 132 + n0w + q + 8] = v2;
        Fs[(b + 1) * 132 + n0w + q + 8] = v3;
    }
    __syncthreads();

    for (int p = tid; p < 64 * KK; p += 256) {
        int b = p / KK, k9 = p % KK;
        const float4* fr = (const float4*)&Fs[b * 132];
        const float4* wr = (const float4*)&Wc[k9 * 128];
        float s = 0.f;
        #pragma unroll
        for (int i = 0; i < 32; ++i) {
            float4 f = fr[i], ww = wr[i];
            s += f.x * ww.x + f.y * ww.y + f.z * ww.z + f.w * ww.w;
        }
        int bg = bh * 64 + b;
        g_em[((size_t)bg * TT + t) * KK + k9] = s + bc[k9];
    }
}

// ---------------- kernel 4: CRF NLL --------------------------------------
__global__ void k_crf(const int* __restrict__ labels,
                      const float* __restrict__ start_t,
                      const float* __restrict__ end_t,
                      const float* __restrict__ trans,
                      float* out)
{
    int b = blockIdx.x;
    int j = threadIdx.x;
    const float* em = g_em + (size_t)b * TT * KK;
    int jj = (j < KK) ? j : 0;
    float tr[KK];
    #pragma unroll
    for (int i = 0; i < KK; ++i) tr[i] = trans[i * KK + jj];

    float alpha = (j < KK) ? (start_t[j] + em[j]) : -1e30f;
    for (int t = 1; t < TT; ++t) {
        float e = (j < KK) ? em[t * KK + j] : 0.f;
        float v[KK];
        float m = -1e30f;
        #pragma unroll
        for (int i = 0; i < KK; ++i) {
            float ai = __shfl_sync(0xffffffffu, alpha, i);
            v[i] = ai + tr[i];
            m = fmaxf(m, v[i]);
        }
        float s = 0.f;
        #pragma unroll
        for (int i = 0; i < KK; ++i) s += expf(v[i] - m);
        float na = m + logf(s) + e;
        alpha = (j < KK) ? na : -1e30f;
    }
    float z = (j < KK) ? (alpha + end_t[j]) : -1e30f;
    float m = z;
    #pragma unroll
    for (int o = 16; o > 0; o >>= 1) m = fmaxf(m, __shfl_xor_sync(0xffffffffu, m, o));
    float s = (j < KK) ? expf(z - m) : 0.f;
    #pragma unroll
    for (int o = 16; o > 0; o >>= 1) s += __shfl_xor_sync(0xffffffffu, s, o);
    float logZ = m + logf(s);

    const int* lb = labels + (size_t)b * TT;
    float part = 0.f;
    for (int t = 1 + j; t < TT; t += 32) {
        int lp = lb[t - 1], lc = lb[t];
        part += trans[lp * KK + lc] + em[t * KK + lc];
    }
    #pragma unroll
    for (int o = 16; o > 0; o >>= 1) part += __shfl_xor_sync(0xffffffffu, part, o);

    if (j == 0) {
        int l0 = lb[0];
        float num = part + start_t[l0] + em[l0] + end_t[lb[TT - 1]];
        atomicAdd(out, logZ - num);
    }
}

// ---------------- host launcher ------------------------------------------
extern "C" void kernel_launch(void* const* d_in, const int* in_sizes, int n_in,
                              void* d_out, int out_size) {
    const float* x      = (const float*)d_in[0];
    const int*   labels = (const int*)d_in[2];
    const float* Wih_f  = (const float*)d_in[4];
    const float* Whh_f  = (const float*)d_in[5];
    const float* b_f    = (const float*)d_in[6];
    const float* Wih_b  = (const float*)d_in[7];
    const float* Whh_b  = (const float*)d_in[8];
    const float* b_b    = (const float*)d_in[9];
    const float* Wlin   = (const float*)d_in[10];
    const float* blin   = (const float*)d_in[11];
    const float* Wcls   = (const float*)d_in[12];
    const float* bcls   = (const float*)d_in[13];
    const float* start_t= (const float*)d_in[14];
    const float* end_t  = (const float*)d_in[15];
    const float* trans  = (const float*)d_in[16];
    float* out = (float*)d_out;

    k_zero<<<64, 256>>>(out, Wlin);
    k_proj<<<16384, 256>>>(x, Wih_f, b_f, Wih_b, b_b);
    k_rnn<<<128, 256>>>(Whh_f, Whh_b);
    k_feats<<<1024, 256>>>(blin, Wcls, bcls);
    k_crf<<<128, 32>>>(labels, start_t, end_t, trans, out);
}

// round 15
// speedup vs baseline: 1.5661x; 1.1928x over previous
#include <cuda_runtime.h>
#include <cuda_bf16.h>
#include <math.h>

#define TT   512
#define BB   128
#define DIN  102
#define HH   256
#define G4   1024
#define DLIN 128
#define KK   9

// ---------------- device scratch ----------------
// gates layout: bf16 [dir][t][col][b]
__device__ __nv_bfloat16 g_gates16[(size_t)2 * TT * G4 * BB];
// h layout: bf16 [dir][slot][b][unit] (unit contiguous)
// fwd: slot t+1 = h(t), slot0 zeros; bwd: slot t = h(t), slot TT zeros
__device__ __nv_bfloat16 g_h16[(size_t)2 * (TT + 1) * BB * HH];
__device__ float g_em[(size_t)BB * TT * KK];
__device__ unsigned int g_bar8[8];
// Wlin pre-converted to bf16 pairs
__device__ unsigned g_wlin16[DLIN * 512 / 2];

__device__ __forceinline__ float d2t(float x) {
    float r;
    asm("cvt.rna.tf32.f32 %0, %1;" : "=f"(r) : "f"(x));
    return r;
}
__device__ __forceinline__ unsigned pk2(float lo, float hi) {
    __nv_bfloat162 t = __floats2bfloat162_rn(lo, hi);
    return *(unsigned*)&t;
}
__device__ __forceinline__ float2 upk2(unsigned u) {
    __nv_bfloat162 t = *(__nv_bfloat162*)&u;
    return __bfloat1622float2(t);
}
__device__ __forceinline__ void mma8(float* d, const float* a, float b0, float b1) {
    asm volatile(
        "mma.sync.aligned.m16n8k8.row.col.f32.tf32.tf32.f32 "
        "{%0,%1,%2,%3}, {%4,%5,%6,%7}, {%8,%9}, {%0,%1,%2,%3};\n"
        : "+f"(d[0]), "+f"(d[1]), "+f"(d[2]), "+f"(d[3])
        : "r"(__float_as_uint(a[0])), "r"(__float_as_uint(a[1])),
          "r"(__float_as_uint(a[2])), "r"(__float_as_uint(a[3])),
          "r"(__float_as_uint(b0)), "r"(__float_as_uint(b1)));
}
__device__ __forceinline__ void mma16(float* d, const unsigned* a,
                                      unsigned b0, unsigned b1) {
    asm volatile(
        "mma.sync.aligned.m16n8k16.row.col.f32.bf16.bf16.f32 "
        "{%0,%1,%2,%3}, {%4,%5,%6,%7}, {%8,%9}, {%0,%1,%2,%3};\n"
        : "+f"(d[0]), "+f"(d[1]), "+f"(d[2]), "+f"(d[3])
        : "r"(a[0]), "r"(a[1]), "r"(a[2]), "r"(a[3]),
          "r"(b0), "r"(b1));
}
__device__ __forceinline__ float tanha(float x) {
    float r;
    asm("tanh.approx.f32 %0, %1;" : "=f"(r) : "f"(x));
    return r;
}
__device__ __forceinline__ float sig2(float x) {
    return fmaf(tanha(0.5f * x), 0.5f, 0.5f);
}
__device__ __forceinline__ float sigf(float x)  { return 1.f / (1.f + __expf(-x)); }

// ---------------- kernel 0: init + Wlin bf16 pre-convert -----------------
__global__ void k_zero(float* out, const float* __restrict__ Wlin) {
    int idx = blockIdx.x * blockDim.x + threadIdx.x;
    int stride = gridDim.x * blockDim.x;
    if (idx == 0) out[0] = 0.f;
    if (idx < 8) g_bar8[idx] = 0u;
    const int HBW = BB * HH / 2;
    unsigned* hf0 = (unsigned*)g_h16;
    unsigned* hbT = (unsigned*)(g_h16 + (size_t)((TT + 1) + TT) * BB * HH);
    for (int i = idx; i < HBW; i += stride) { hf0[i] = 0u; hbT[i] = 0u; }
    for (int i = idx; i < DLIN * 512 / 2; i += stride) {
        float2 v = ((const float2*)Wlin)[i];
        g_wlin16[i] = pk2(v.x, v.y);
    }
}

// ---------------- kernel 1: gates = x @ Wih^T + b  (tf32 mma, bf16 out) --
__global__ void __launch_bounds__(256) k_proj(
    const float* __restrict__ x,
    const float* __restrict__ Wih_f, const float* __restrict__ b_f,
    const float* __restrict__ Wih_b, const float* __restrict__ b_b)
{
    unsigned bx = blockIdx.x;
    int bh   = bx & 1;
    int colt = (bx >> 1) & 7;
    int t    = (bx >> 4) & 511;
    int dir  = bx >> 13;
    const float* Wih  = dir ? Wih_b : Wih_f;
    const float* bias = dir ? b_b : b_f;
    int col0 = colt * 128;
    int tid = threadIdx.x;
    int lane = tid & 31, w = tid >> 5;
    int q = lane >> 2, tg = lane & 3;
    int rowA = col0 + w * 16 + q;
    int rowB = rowA + 8;

    __shared__ float xs[104][72];

    float aF[13][4];
    #pragma unroll
    for (int kk = 0; kk < 13; ++kk) {
        int k = kk * 8 + tg;
        aF[kk][0] = (k < DIN)     ? d2t(Wih[(size_t)rowA * DIN + k])     : 0.f;
        aF[kk][1] = (k < DIN)     ? d2t(Wih[(size_t)rowB * DIN + k])     : 0.f;
        aF[kk][2] = (k + 4 < DIN) ? d2t(Wih[(size_t)rowA * DIN + k + 4]) : 0.f;
        aF[kk][3] = (k + 4 < DIN) ? d2t(Wih[(size_t)rowB * DIN + k + 4]) : 0.f;
    }
    for (int i = tid; i < 2 * 64; i += 256) xs[102 + (i >> 6)][i & 63] = 0.f;
    for (int f = tid; f < 64 * DIN; f += 256) {
        int b = f / DIN, d = f - b * DIN;
        xs[d][b] = d2t(x[((size_t)(bh * 64 + b) * TT + t) * DIN + d]);
    }
    __syncthreads();

    float acc[8][4];
    #pragma unroll
    for (int nt = 0; nt < 8; ++nt)
        #pragma unroll
        for (int j = 0; j < 4; ++j) acc[nt][j] = 0.f;

    #pragma unroll
    for (int kk = 0; kk < 13; ++kk) {
        #pragma unroll
        for (int nt = 0; nt < 8; ++nt) {
            float b0 = xs[kk * 8 + tg][nt * 8 + q];
            float b1 = xs[kk * 8 + tg + 4][nt * 8 + q];
            mma8(acc[nt], aF[kk], b0, b1);
        }
    }

    float bA = bias[rowA], bB = bias[rowB];
    __nv_bfloat16* gt = g_gates16 + ((size_t)(dir * TT + t)) * (G4 * BB);
    #pragma unroll
    for (int nt = 0; nt < 8; ++nt) {
        int cb = bh * 64 + nt * 8 + 2 * tg;
        *(unsigned*)&gt[(size_t)rowA * BB + cb] = pk2(acc[nt][0] + bA, acc[nt][1] + bA);
        *(unsigned*)&gt[(size_t)rowB * BB + cb] = pk2(acc[nt][2] + bB, acc[nt][3] + bB);
    }
}

// ---------------- kernel 2: persistent BiLSTM, bf16 mma ------------------
// 128 CTAs = dir(2) x ug(16) x bq(4); 256 thr; CTA tile 64 gate rows
// (16 units x 4 gates) x 32 batch. 8 barrier groups (dir x bq), 16 arrivals.
// Sync structure identical to R11 (single red.release + tid0 poll).
__global__ void __launch_bounds__(256, 1) k_rnn(
    const float* __restrict__ Whh_f, const float* __restrict__ Whh_b)
{
    int tid  = threadIdx.x;
    int lane = tid & 31, w = tid >> 5;
    int mg = w >> 1;                  // 0..3: (gatepair, unit-octet)
    int gp = mg >> 1;                 // 0..1: gates (i,g) pair index
    int uo = mg & 1;                  // 0..1: unit octet
    int ng = w & 1;                   // 0..1: 16-batch group
    int dir = blockIdx.x >> 6;
    int sub = blockIdx.x & 63;
    int ug  = sub >> 2;               // 0..15
    int bq  = sub & 3;                // 0..3
    int u0  = ug * 16;
    int boff = bq * 32;
    const float* Whh = dir ? Whh_b : Whh_f;

    __shared__ unsigned hsW[32 * 132];        // h tile [b32][k] bf16 pairs
    __shared__ float outs[64 * 36];           // [gate*16+unit][b32]
    __shared__ float csh[16 * 32];            // cell state [u][b]
    __shared__ __nv_bfloat16 hb[32][16];      // h out staging [b][u]

    int q  = lane >> 2;
    int tg = lane & 3;
    int rowA = (2 * gp) * 256 + u0 + uo * 8 + q;   // gate 2gp
    int rowB = rowA + 256;                          // gate 2gp+1
    int n0 = ng * 16;

    // bf16 A fragments: 16 rows x 256 k in 64 regs
    unsigned aF[16][4];
    {
        const float* WA = Whh + (size_t)rowA * HH;
        const float* WB = Whh + (size_t)rowB * HH;
        #pragma unroll
        for (int kk = 0; kk < 16; ++kk) {
            int k0 = kk * 16 + 2 * tg;
            float2 a0 = *(const float2*)&WA[k0];
            float2 a1 = *(const float2*)&WB[k0];
            float2 a2 = *(const float2*)&WA[k0 + 8];
            float2 a3 = *(const float2*)&WB[k0 + 8];
            aF[kk][0] = pk2(a0.x, a0.y);
            aF[kk][1] = pk2(a1.x, a1.y);
            aF[kk][2] = pk2(a2.x, a2.y);
            aF[kk][3] = pk2(a3.x, a3.y);
        }
    }
    for (int i = tid; i < 16 * 32; i += 256) csh[i] = 0.f;
    __syncthreads();

    const size_t HB = (size_t)BB * HH;
    __nv_bfloat16* harr = g_h16 + (size_t)dir * (TT + 1) * HB;
    const __nv_bfloat16* gbase = g_gates16 + (size_t)dir * TT * (size_t)(G4 * BB);
    unsigned bidx = (unsigned)(dir * 4 + bq);
    unsigned int* barp = &g_bar8[bidx];
    int cb = boff + n0 + 2 * tg;

    unsigned gAu[2], gBu[2];
    {
        int t0 = dir ? (TT - 1) : 0;
        const __nv_bfloat16* gt = gbase + (size_t)t0 * (G4 * BB);
        #pragma unroll
        for (int nt = 0; nt < 2; ++nt) {
            gAu[nt] = *(const unsigned*)&gt[(size_t)rowA * BB + cb + nt * 8];
            gBu[nt] = *(const unsigned*)&gt[(size_t)rowB * BB + cb + nt * 8];
        }
    }

    int hrow = tid >> 3;      // 0..31
    int hc8  = tid & 7;       // base 16B column

    for (int s = 0; s < TT; ++s) {
        int t = dir ? (TT - 1 - s) : s;
        const __nv_bfloat16* hin = harr + (size_t)(dir ? (t + 1) : t) * HB
                                        + (size_t)boff * HH;
        __nv_bfloat16* hout = harr + (size_t)(dir ? t : (t + 1)) * HB;

        // stage h tile [32 b][256 k] bf16 -> smem (4 LDG.128/thread)
        uint4 v[4];
        #pragma unroll
        for (int i = 0; i < 4; ++i)
            v[i] = *(const uint4*)(hin + (size_t)hrow * HH + (hc8 + 8 * i) * 8);
        #pragma unroll
        for (int i = 0; i < 4; ++i)
            *(uint4*)&hsW[hrow * 132 + (hc8 + 8 * i) * 4] = v[i];
        __syncthreads();

        float acc[2][4];
        #pragma unroll
        for (int nt = 0; nt < 2; ++nt) {
            float2 fa = upk2(gAu[nt]);
            float2 fb = upk2(gBu[nt]);
            acc[nt][0] = fa.x; acc[nt][1] = fa.y;
            acc[nt][2] = fb.x; acc[nt][3] = fb.y;
        }
        #pragma unroll
        for (int kk = 0; kk < 16; ++kk) {
            #pragma unroll
            for (int nt = 0; nt < 2; ++nt) {
                int base = (n0 + nt * 8 + q) * 132 + kk * 8 + tg;
                mma16(acc[nt], aF[kk], hsW[base], hsW[base + 4]);
            }
        }

        // stage pre-activations: rows gate*16+unit
        int rowI = (2 * gp) * 16 + uo * 8 + q;
        #pragma unroll
        for (int nt = 0; nt < 2; ++nt) {
            *(float2*)&outs[rowI * 36 + n0 + nt * 8 + 2 * tg] =
                make_float2(acc[nt][0], acc[nt][1]);
            *(float2*)&outs[(rowI + 16) * 36 + n0 + nt * 8 + 2 * tg] =
                make_float2(acc[nt][2], acc[nt][3]);
        }
        __syncthreads();

        // LSTM cell epilogue: 16 units x 32 cols
        #pragma unroll
        for (int rep = 0; rep < 2; ++rep) {
            int p = tid + rep * 256;
            int u = p >> 5, cc = p & 31;
            float iv = outs[u * 36 + cc];
            float fv = outs[(16 + u) * 36 + cc];
            float gv = outs[(32 + u) * 36 + cc];
            float ov = outs[(48 + u) * 36 + cc];
            float c = sig2(fv) * csh[u * 32 + cc] + sig2(iv) * tanha(gv);
            csh[u * 32 + cc] = c;
            float h = sig2(ov) * tanha(c);
            hb[cc][u] = __float2bfloat16_rn(h);
        }
        __syncthreads();

        // cooperative h writeback: 64 threads x 16B
        if (tid < 64) {
            int row = tid >> 1, part = tid & 1;
            uint4 hv = *(uint4*)&hb[row][part * 8];
            *(uint4*)(hout + (size_t)(boff + row) * HH + u0 + part * 8) = hv;
        }
        __syncthreads();
        if (tid == 0) {
            unsigned one = 1u;
            asm volatile("red.release.gpu.global.add.u32 [%0], %1;"
                         :: "l"(barp), "r"(one) : "memory");
        }

        // prefetch next step's gates while the barrier drains
        if (s + 1 < TT) {
            int tn = dir ? (t - 1) : (t + 1);
            const __nv_bfloat16* gt = gbase + (size_t)tn * (G4 * BB);
            #pragma unroll
            for (int nt = 0; nt < 2; ++nt) {
                gAu[nt] = *(const unsigned*)&gt[(size_t)rowA * BB + cb + nt * 8];
                gBu[nt] = *(const unsigned*)&gt[(size_t)rowB * BB + cb + nt * 8];
            }
        }
        if (tid == 0) {
            unsigned target = (unsigned)(s + 1) * 16u;
            while (*((volatile unsigned int*)barp) < target) {}
        }
        __syncthreads();
    }
}

// ---------------- kernel 3: feats + emissions (bf16 mma, double-buffered) -
__global__ void __launch_bounds__(256) k_feats(
    const float* __restrict__ blin,
    const float* __restrict__ Wcls, const float* __restrict__ bcls)
{
    unsigned bx = blockIdx.x;
    int bh = bx & 1;
    int t  = bx >> 1;
    int tid = threadIdx.x;
    int lane = tid & 31, w = tid >> 5;
    int q = lane >> 2, tg = lane & 3;

    __shared__ float smem[9616];
    unsigned* hsW = (unsigned*)smem;          // phase1: [64 b][36w]
    unsigned* Ws2 = (unsigned*)(smem + 2304); // phase1: [128 n][36w]
    float* Fs = smem;                         // phase2: [64][132]
    float* Wc = smem + 8448;                  // [9][128]
    float* bc = smem + 9600;                  // [9]

    for (int i = tid; i < KK * DLIN; i += 256) Wc[i] = Wcls[i];
    if (tid < KK) bc[tid] = bcls[tid];

    int n0w = w * 16;
    float acc[8][4];
    #pragma unroll
    for (int nt = 0; nt < 8; ++nt)
        #pragma unroll
        for (int j = 0; j < 4; ++j) acc[nt][j] = 0.f;

    const size_t HB = (size_t)BB * HH;
    const __nv_bfloat16* hf = g_h16 + (size_t)(t + 1) * HB + (size_t)(bh * 64) * HH;
    const __nv_bfloat16* hb = g_h16 + (size_t)(TT + 1) * HB + (size_t)t * HB
                                    + (size_t)(bh * 64) * HH;
    const uint4* wl4 = (const uint4*)g_wlin16;

    int hrow0 = tid >> 3, hc8 = tid & 7;
    int wrow = tid >> 1, wpart = tid & 1;

    uint4 hv[2], wv[4];
    {
        #pragma unroll
        for (int i = 0; i < 2; ++i)
            hv[i] = *(const uint4*)(hf + (size_t)(hrow0 + 32 * i) * HH + hc8 * 8);
        #pragma unroll
        for (int j = 0; j < 4; ++j)
            wv[j] = wl4[wrow * 64 + wpart * 4 + j];
    }

    for (int kc = 0; kc < 8; ++kc) {
        __syncthreads();
        #pragma unroll
        for (int i = 0; i < 2; ++i)
            *(uint4*)&hsW[(hrow0 + 32 * i) * 36 + hc8 * 4] = hv[i];
        #pragma unroll
        for (int j = 0; j < 4; ++j)
            *(uint4*)&Ws2[wrow * 36 + wpart * 16 + j * 4] = wv[j];
        __syncthreads();

        if (kc + 1 < 8) {
            int kn = kc + 1;
            int kbase = (kn & 3) * 64;
            const __nv_bfloat16* hsrc = (kn < 4) ? hf : hb;
            #pragma unroll
            for (int i = 0; i < 2; ++i)
                hv[i] = *(const uint4*)(hsrc + (size_t)(hrow0 + 32 * i) * HH + kbase + hc8 * 8);
            #pragma unroll
            for (int j = 0; j < 4; ++j)
                wv[j] = wl4[wrow * 64 + kn * 8 + wpart * 4 + j];
        }

        #pragma unroll
        for (int kk = 0; kk < 4; ++kk) {
            unsigned a[4];
            int ab = (n0w + q) * 36 + kk * 8 + tg;
            a[0] = Ws2[ab];
            a[1] = Ws2[ab + 8 * 36];
            a[2] = Ws2[ab + 4];
            a[3] = Ws2[ab + 8 * 36 + 4];
            #pragma unroll
            for (int nt = 0; nt < 8; ++nt) {
                int bbse = (nt * 8 + q) * 36 + kk * 8 + tg;
                mma16(acc[nt], a, hsW[bbse], hsW[bbse + 4]);
            }
        }
    }
    __syncthreads();

    float blA = blin[n0w + q], blB = blin[n0w + q + 8];
    #pragma unroll
    for (int nt = 0; nt < 8; ++nt) {
        int b = nt * 8 + 2 * tg;
        float v0 = acc[nt][0] + blA;
        float v1 = acc[nt][1] + blA;
        float v2 = acc[nt][2] + blB;
        float v3 = acc[nt][3] + blB;
        v0 = (v0 > 0.f) ? v0 : expm1f(v0);
        v1 = (v1 > 0.f) ? v1 : expm1f(v1);
        v2 = (v2 > 0.f) ? v2 : expm1f(v2);
        v3 = (v3 > 0.f) ? v3 : expm1f(v3);
        Fs[b * 132 + n0w + q] = v0;
        Fs[(b + 1) * 132 + n0w + q] = v1;
        Fs[b * 132 + n0w + q + 8] = v2;
        Fs[(b + 1) * 132 + n0w + q + 8] = v3;
    }
    __syncthreads();

    for (int p = tid; p < 64 * KK; p += 256) {
        int b = p / KK, k9 = p % KK;
        const float4* fr = (const float4*)&Fs[b * 132];
        const float4* wr = (const float4*)&Wc[k9 * 128];
        float s = 0.f;
        #pragma unroll
        for (int i = 0; i < 32; ++i) {
            float4 f = fr[i], ww = wr[i];
            s += f.x * ww.x + f.y * ww.y + f.z * ww.z + f.w * ww.w;
        }
        int bg = bh * 64 + b;
        g_em[((size_t)bg * TT + t) * KK + k9] = s + bc[k9];
    }
}

// ---------------- kernel 4: CRF NLL --------------------------------------
__global__ void k_crf(const int* __restrict__ labels,
                      const float* __restrict__ start_t,
                      const float* __restrict__ end_t,
                      const float* __restrict__ trans,
                      float* out)
{
    int b = blockIdx.x;
    int j = threadIdx.x;
    const float* em = g_em + (size_t)b * TT * KK;
    int jj = (j < KK) ? j : 0;
    float tr[KK];
    #pragma unroll
    for (int i = 0; i < KK; ++i) tr[i] = trans[i * KK + jj];

    float alpha = (j < KK) ? (start_t[j] + em[j]) : -1e30f;
    for (int t = 1; t < TT; ++t) {
        float e = (j < KK) ? em[t * KK + j] : 0.f;
        float v[KK];
        float m = -1e30f;
        #pragma unroll
        for (int i = 0; i < KK; ++i) {
            float ai = __shfl_sync(0xffffffffu, alpha, i);
            v[i] = ai + tr[i];
            m = fmaxf(m, v[i]);
        }
        float s = 0.f;
        #pragma unroll
        for (int i = 0; i < KK; ++i) s += expf(v[i] - m);
        float na = m + logf(s) + e;
        alpha = (j < KK) ? na : -1e30f;
    }
    float z = (j < KK) ? (alpha + end_t[j]) : -1e30f;
    float m = z;
    #pragma unroll
    for (int o = 16; o > 0; o >>= 1) m = fmaxf(m, __shfl_xor_sync(0xffffffffu, m, o));
    float s = (j < KK) ? expf(z - m) : 0.f;
    #pragma unroll
    for (int o = 16; o > 0; o >>= 1) s += __shfl_xor_sync(0xffffffffu, s, o);
    float logZ = m + logf(s);

    const int* lb = labels + (size_t)b * TT;
    float part = 0.f;
    for (int t = 1 + j; t < TT; t += 32) {
        int lp = lb[t - 1], lc = lb[t];
        part += trans[lp * KK + lc] + em[t * KK + lc];
    }
    #pragma unroll
    for (int o = 16; o > 0; o >>= 1) part += __shfl_xor_sync(0xffffffffu, part, o);

    if (j == 0) {
        int l0 = lb[0];
        float num = part + start_t[l0] + em[l0] + end_t[lb[TT - 1]];
        atomicAdd(out, logZ - num);
    }
}

// ---------------- host launcher ------------------------------------------
extern "C" void kernel_launch(void* const* d_in, const int* in_sizes, int n_in,
                              void* d_out, int out_size) {
    const float* x      = (const float*)d_in[0];
    const int*   labels = (const int*)d_in[2];
    const float* Wih_f  = (const float*)d_in[4];
    const float* Whh_f  = (const float*)d_in[5];
    const float* b_f    = (const float*)d_in[6];
    const float* Wih_b  = (const float*)d_in[7];
    const float* Whh_b  = (const float*)d_in[8];
    const float* b_b    = (const float*)d_in[9];
    const float* Wlin   = (const float*)d_in[10];
    const float* blin   = (const float*)d_in[11];
    const float* Wcls   = (const float*)d_in[12];
    const float* bcls   = (const float*)d_in[13];
    const float* start_t= (const float*)d_in[14];
    const float* end_t  = (const float*)d_in[15];
    const float* trans  = (const float*)d_in[16];
    float* out = (float*)d_out;

    k_zero<<<64, 256>>>(out, Wlin);
    k_proj<<<16384, 256>>>(x, Wih_f, b_f, Wih_b, b_b);
    k_rnn<<<128, 256>>>(Whh_f, Whh_b);
    k_feats<<<1024, 256>>>(blin, Wcls, bcls);
    k_crf<<<128, 32>>>(labels, start_t, end_t, trans, out);
}